// round 13
// baseline (speedup 1.0000x reference)
#include <cuda_runtime.h>
#include <cstdint>

#define NN      100000
#define NE      400000
#define IN_CHN  1024
#define FC      128
#define OC      3
#define NEG_SLOPE 0.01f

// ---------------- scratch (static device globals; no allocation) ------------
__device__ __align__(16) float g_Yl[(size_t)NN * FC];   // X @ W1_l
__device__ __align__(16) float g_Yr[(size_t)NN * FC];   // X @ W1_r
__device__ __align__(16) float g_S [(size_t)NN * FC];   // segment-sum of Yl
__device__ __align__(16) float g_x1[(size_t)NN * FC];   // layer-1 output
__device__ __align__(16) float g_deg[NN];
__device__ __align__(16) float g_Wt[256 * IN_CHN];      // [Wl|Wr]^T, K-major, tf32
__device__ __align__(16) float g_Zl[NN * OC + 4];
__device__ __align__(16) float g_Zr[NN * OC + 4];
__device__ __align__(16) float g_S2[NN * OC + 4];

__device__ __forceinline__ uint32_t f2tf32(float x) {
    uint32_t r;
    asm("cvt.rna.tf32.f32 %0, %1;" : "=r"(r) : "f"(x));
    return r;
}
__device__ __forceinline__ uint32_t smem_u32(const void* p) {
    uint32_t a;
    asm("{ .reg .u64 t; cvta.to.shared.u64 t, %1; cvt.u32.u64 %0, t; }" : "=r"(a) : "l"(p));
    return a;
}
__device__ __forceinline__ void ldsm4(uint32_t* r, uint32_t addr) {
    asm volatile("ldmatrix.sync.aligned.m8n8.x4.shared.b16 {%0,%1,%2,%3}, [%4];"
        : "=r"(r[0]), "=r"(r[1]), "=r"(r[2]), "=r"(r[3]) : "r"(addr));
}
__device__ __forceinline__ void mma_tf32(float* c, const uint32_t* a, const uint32_t* b) {
    asm volatile(
        "mma.sync.aligned.m16n8k8.row.col.f32.tf32.tf32.f32 "
        "{%0,%1,%2,%3}, {%4,%5,%6,%7}, {%8,%9}, {%0,%1,%2,%3};"
        : "+f"(c[0]), "+f"(c[1]), "+f"(c[2]), "+f"(c[3])
        : "r"(a[0]), "r"(a[1]), "r"(a[2]), "r"(a[3]), "r"(b[0]), "r"(b[1]));
}

// ============ tf32 mma.sync GEMM: Y[:,128] = X[NN,1024] @ Wt_half^T =========
// CTA tile 128M x 128N, BK=32, double-buffered, row-major + XOR-swizzled SMEM,
// ldmatrix-fed fragments. grid.x folds (mtile, z): z = bid & 1 -> Yl / Yr
// (adjacent bids share the A tile through L2).
//
// SMEM stage (32 KB): A 128 rows x 128B (tf32), B 128 rows x 128B.
// Swizzle: 16B-word w at row r lives at byte r*128 + ((w ^ (r&7))<<4).
#define GBK 32
#define NIT (IN_CHN / GBK)          // 32
#define STAGE_B 32768
#define GEMM_SMEM (2 * STAGE_B)     // 64 KB

__global__ void __launch_bounds__(256, 2)
gemm1_mma_kernel(const float* __restrict__ A)
{
    extern __shared__ char smc[];
    const uint32_t sbase = smem_u32(smc);
    const int tid = threadIdx.x;
    const int lane = tid & 31;
    const int wid = tid >> 5;
    const int warp_m = wid & 3;          // 0..3 (32 rows each)
    const int warp_n = wid >> 2;         // 0..1 (64 cols each)
    const int mtile = blockIdx.x >> 1;
    const int z     = blockIdx.x & 1;
    const int m0 = mtile * 128;
    const float* __restrict__ Bsrc = g_Wt + (size_t)z * 128 * IN_CHN;

    float acc[2][8][4];
    #pragma unroll
    for (int i = 0; i < 2; i++)
        #pragma unroll
        for (int j = 0; j < 8; j++)
            #pragma unroll
            for (int q = 0; q < 4; q++) acc[i][j][q] = 0.f;

    // staging indices: e4 = tid + p*256, row = e4>>3 (0..127), c4 = e4&7
    const int s_row = tid >> 3;          // row for p=0 (rows advance by 32 per p)
    const int s_c4  = tid & 7;

    auto stage = [&](int it, char* buf) {
        const int k0 = it * GBK;
        #pragma unroll
        for (int p = 0; p < 4; p++) {
            const int row = s_row + p * 32;
            const uint32_t soff = (uint32_t)row * 128 + (uint32_t)((s_c4 ^ (row & 7)) << 4);
            // A (convert to tf32)
            {
                int m = m0 + row;
                float4 v = make_float4(0.f, 0.f, 0.f, 0.f);
                if (m < NN) v = *(const float4*)(A + (size_t)m * IN_CHN + k0 + s_c4 * 4);
                uint4 t = make_uint4(f2tf32(v.x), f2tf32(v.y), f2tf32(v.z), f2tf32(v.w));
                *(uint4*)(buf + soff) = t;
            }
            // B (already tf32 in g_Wt)
            {
                uint4 t = *(const uint4*)(Bsrc + (size_t)row * IN_CHN + k0 + s_c4 * 4);
                *(uint4*)(buf + 16384 + soff) = t;
            }
        }
    };

    // ---- precomputed ldmatrix lane addressing (byte offsets within a stage) --
    // A matrices: id = lane>>3; for mfrag i: row = (warp_m*2+i)*16 + (id&1)*8 + (lane&7)
    //             word = ks*2 + (id>>1)
    const int lm_id   = lane >> 3;
    const int a_row0  = warp_m * 32 + (lm_id & 1) * 8 + (lane & 7);   // mfrag i adds i*16
    const int a_wsel  = lm_id >> 1;
    // B matrices: nf = warp_n*8 + p*2 + (id>>1); word = ks*2 + (id&1)
    //             row = nf*8 + (lane&7)
    const int b_row0  = warp_n * 64 + (lm_id >> 1) * 8 + (lane & 7);  // pair p adds p*16
    const int b_wsel  = lm_id & 1;

    stage(0, smc);
    __syncthreads();

    for (int it = 0; it < NIT; it++) {
        if (it + 1 < NIT) stage(it + 1, smc + ((it + 1) & 1) * STAGE_B);

        const uint32_t buf = sbase + (uint32_t)((it & 1) * STAGE_B);
        #pragma unroll
        for (int ks = 0; ks < 4; ks++) {
            uint32_t a[2][4];
            #pragma unroll
            for (int i = 0; i < 2; i++) {
                int row = a_row0 + i * 16;
                int w   = ks * 2 + a_wsel;
                ldsm4(a[i], buf + row * 128 + (((uint32_t)(w ^ (row & 7))) << 4));
            }
            uint32_t b[8][2];
            #pragma unroll
            for (int p = 0; p < 4; p++) {
                int row = b_row0 + p * 16;
                int w   = ks * 2 + b_wsel;
                uint32_t r[4];
                ldsm4(r, buf + 16384 + row * 128 + (((uint32_t)(w ^ (row & 7))) << 4));
                b[p * 2 + 0][0] = r[0];
                b[p * 2 + 0][1] = r[1];
                b[p * 2 + 1][0] = r[2];
                b[p * 2 + 1][1] = r[3];
            }
            #pragma unroll
            for (int i = 0; i < 2; i++)
                #pragma unroll
                for (int j = 0; j < 8; j++)
                    mma_tf32(acc[i][j], a[i], b[j]);
        }
        __syncthreads();
    }

    // ---- epilogue ----
    float* __restrict__ C = z ? g_Yr : g_Yl;
    const int g = lane >> 2, tig = lane & 3;
    #pragma unroll
    for (int i = 0; i < 2; i++) {
        int r0 = m0 + warp_m * 32 + i * 16 + g;
        #pragma unroll
        for (int j = 0; j < 8; j++) {
            int col = warp_n * 64 + j * 8 + tig * 2;
            if (r0 < NN)
                *(float2*)(C + (size_t)r0 * FC + col) = make_float2(acc[i][j][0], acc[i][j][1]);
            if (r0 + 8 < NN)
                *(float2*)(C + (size_t)(r0 + 8) * FC + col) = make_float2(acc[i][j][2], acc[i][j][3]);
        }
    }
}

// ---------------- prep: g_Wt[n][k] = tf32(W[k][n]) ---------------------------
__global__ void prep_wt_kernel(const float* __restrict__ Wl, const float* __restrict__ Wr) {
    int i = blockIdx.x * blockDim.x + threadIdx.x;
    if (i >= 256 * IN_CHN) return;
    int n = i >> 10;
    int k = i & 1023;
    float v = (n < FC) ? Wl[(size_t)k * FC + n] : Wr[(size_t)k * FC + (n - FC)];
    g_Wt[i] = __uint_as_float(f2tf32(v));
}

// ---------------- 0) zero the accumulators ---------------------------------
__global__ void zero_kernel() {
    size_t stride = (size_t)gridDim.x * blockDim.x;
    size_t i = (size_t)blockIdx.x * blockDim.x + threadIdx.x;
    for (size_t j = i; j < (size_t)NN * FC; j += stride) g_S[j] = 0.f;
    for (size_t j = i; j < (size_t)NN;      j += stride) g_deg[j] = 0.f;
    for (size_t j = i; j < (size_t)NN * OC; j += stride) g_S2[j] = 0.f;
}

// ---------------- 1) in-degree ----------------------------------------------
__global__ void deg_kernel(const int* __restrict__ edges) {
    int i = blockIdx.x * blockDim.x + threadIdx.x;
    if (i < NE) atomicAdd(&g_deg[edges[NE + i]], 1.0f);
}

// ---------------- 3) edge aggregation layer 1: S[dst] += Yl[src] -----------
// one warp per edge; lane holds a float4; vector reduction (sm_90+)
__global__ void agg1_kernel(const int* __restrict__ edges) {
    int gtid = blockIdx.x * blockDim.x + threadIdx.x;
    int e    = gtid >> 5;
    int lane = gtid & 31;
    if (e >= NE) return;
    int src = edges[e];
    int dst = edges[NE + e];
    float4 v = ((const float4*)(g_Yl + (size_t)src * FC))[lane];
    float* s = g_S + (size_t)dst * FC + lane * 4;
    asm volatile("red.global.add.v4.f32 [%0], {%1, %2, %3, %4};"
                 :: "l"(s), "f"(v.x), "f"(v.y), "f"(v.z), "f"(v.w) : "memory");
}

// ---------------- 4) x1 = leaky_relu(S/max(deg,1) + Yr + b1) ----------------
__global__ void finish1_kernel(const float* __restrict__ b1) {
    int i = blockIdx.x * blockDim.x + threadIdx.x;
    if (i >= NN * FC / 4) return;
    int node = i >> 5;
    int c4   = i & 31;
    float inv = 1.f / fmaxf(g_deg[node], 1.f);
    float4 s  = ((const float4*)g_S)[i];
    float4 yr = ((const float4*)g_Yr)[i];
    float4 b  = ((const float4*)b1)[c4];
    float4 o;
    o.x = s.x * inv + yr.x + b.x;
    o.y = s.y * inv + yr.y + b.y;
    o.z = s.z * inv + yr.z + b.z;
    o.w = s.w * inv + yr.w + b.w;
    o.x = o.x >= 0.f ? o.x : NEG_SLOPE * o.x;
    o.y = o.y >= 0.f ? o.y : NEG_SLOPE * o.y;
    o.z = o.z >= 0.f ? o.z : NEG_SLOPE * o.z;
    o.w = o.w >= 0.f ? o.w : NEG_SLOPE * o.w;
    ((float4*)g_x1)[i] = o;
}

// ---------------- 5) tiny GEMM layer 2 --------------------------------------
__global__ void gemm2_kernel(const float* __restrict__ W2l,
                             const float* __restrict__ W2r) {
    __shared__ float sWl[FC * OC];
    __shared__ float sWr[FC * OC];
    for (int t = threadIdx.x; t < FC * OC; t += blockDim.x) {
        sWl[t] = W2l[t];
        sWr[t] = W2r[t];
    }
    __syncthreads();

    int gtid = blockIdx.x * blockDim.x + threadIdx.x;
    int node = gtid >> 5;
    int lane = gtid & 31;
    if (node >= NN) return;

    float4 v = ((const float4*)(g_x1 + (size_t)node * FC))[lane];
    float vx[4] = {v.x, v.y, v.z, v.w};
    float al[OC] = {0.f, 0.f, 0.f};
    float arr[OC] = {0.f, 0.f, 0.f};
    #pragma unroll
    for (int u = 0; u < 4; u++) {
        int k = lane * 4 + u;
        #pragma unroll
        for (int c = 0; c < OC; c++) {
            al[c]  = fmaf(vx[u], sWl[k * OC + c], al[c]);
            arr[c] = fmaf(vx[u], sWr[k * OC + c], arr[c]);
        }
    }
    #pragma unroll
    for (int off = 16; off > 0; off >>= 1) {
        #pragma unroll
        for (int c = 0; c < OC; c++) {
            al[c]  += __shfl_xor_sync(0xFFFFFFFFu, al[c],  off);
            arr[c] += __shfl_xor_sync(0xFFFFFFFFu, arr[c], off);
        }
    }
    if (lane == 0) {
        #pragma unroll
        for (int c = 0; c < OC; c++) {
            g_Zl[node * OC + c] = al[c];
            g_Zr[node * OC + c] = arr[c];
        }
    }
}

// ---------------- 6) edge aggregation layer 2 -------------------------------
__global__ void agg2_kernel(const int* __restrict__ edges) {
    int e = blockIdx.x * blockDim.x + threadIdx.x;
    if (e >= NE) return;
    int src = edges[e];
    int dst = edges[NE + e];
    #pragma unroll
    for (int c = 0; c < OC; c++)
        atomicAdd(&g_S2[dst * OC + c], g_Zl[src * OC + c]);
}

// ---------------- 7) out = S2/max(deg,1) + Zr + b2 ---------------------------
__global__ void final_kernel(const float* __restrict__ b2,
                             float* __restrict__ out) {
    int i = blockIdx.x * blockDim.x + threadIdx.x;
    if (i >= NN * OC) return;
    int node = i / OC;
    int c = i - node * OC;
    float inv = 1.f / fmaxf(g_deg[node], 1.f);
    out[i] = g_S2[i] * inv + g_Zr[i] + b2[c];
}

// ---------------- launch -----------------------------------------------------
extern "C" void kernel_launch(void* const* d_in, const int* in_sizes, int n_in,
                              void* d_out, int out_size) {
    const float* features = (const float*)d_in[0];
    const int*   edges2   = (const int*)d_in[2];   // int32 (jax default, no x64)
    const float* W1_l     = (const float*)d_in[5];
    const float* W1_r     = (const float*)d_in[6];
    const float* b1       = (const float*)d_in[7];
    const float* W2_l     = (const float*)d_in[8];
    const float* W2_r     = (const float*)d_in[9];
    const float* b2       = (const float*)d_in[10];
    float*       out      = (float*)d_out;

    static bool attr_set = false;
    if (!attr_set) {
        cudaFuncSetAttribute(gemm1_mma_kernel,
                             cudaFuncAttributeMaxDynamicSharedMemorySize, GEMM_SMEM);
        attr_set = true;
    }

    zero_kernel<<<2048, 256>>>();
    deg_kernel<<<(NE + 255) / 256, 256>>>(edges2);
    prep_wt_kernel<<<(256 * IN_CHN + 255) / 256, 256>>>(W1_l, W1_r);

    gemm1_mma_kernel<<<((NN + 127) / 128) * 2, 256, GEMM_SMEM>>>(features);

    agg1_kernel<<<(NE * 32 + 255) / 256, 256>>>(edges2);
    finish1_kernel<<<(NN * FC / 4 + 255) / 256, 256>>>(b1);
    gemm2_kernel<<<(NN * 32 + 255) / 256, 256>>>(W2_l, W2_r);
    agg2_kernel<<<(NE + 255) / 256, 256>>>(edges2);
    final_kernel<<<(NN * OC + 255) / 256, 256>>>(b2, out);
}

// round 14
// speedup vs baseline: 1.0002x; 1.0002x over previous
#include <cuda_runtime.h>
#include <cstdint>

#define NN      100000
#define NE      400000
#define IN_CHN  1024
#define FC      128
#define OC      3
#define NEG_SLOPE 0.01f

// ---------------- scratch (static device globals; no allocation) ------------
__device__ __align__(16) float g_Yl[(size_t)NN * FC];   // X @ W1_l
__device__ __align__(16) float g_Yr[(size_t)NN * FC];   // X @ W1_r
__device__ __align__(16) float g_S [(size_t)NN * FC];   // segment-sum of Yl
__device__ __align__(16) float g_x1[(size_t)NN * FC];   // layer-1 output
__device__ __align__(16) float g_deg[NN];
__device__ __align__(16) float g_Wt[256 * IN_CHN];      // [Wl|Wr]^T, K-major, tf32
__device__ __align__(16) float g_Zl[NN * OC + 4];
__device__ __align__(16) float g_Zr[NN * OC + 4];
__device__ __align__(16) float g_S2[NN * OC + 4];

__device__ __forceinline__ uint32_t f2tf32(float x) {
    uint32_t r;
    asm("cvt.rna.tf32.f32 %0, %1;" : "=r"(r) : "f"(x));
    return r;
}
__device__ __forceinline__ uint32_t smem_u32(const void* p) {
    uint32_t a;
    asm("{ .reg .u64 t; cvta.to.shared.u64 t, %1; cvt.u32.u64 %0, t; }" : "=r"(a) : "l"(p));
    return a;
}
__device__ __forceinline__ void ldsm4(uint32_t* r, uint32_t addr) {
    asm volatile("ldmatrix.sync.aligned.m8n8.x4.shared.b16 {%0,%1,%2,%3}, [%4];"
        : "=r"(r[0]), "=r"(r[1]), "=r"(r[2]), "=r"(r[3]) : "r"(addr));
}
__device__ __forceinline__ void mma_tf32(float* c, const uint32_t* a, const uint32_t* b) {
    asm volatile(
        "mma.sync.aligned.m16n8k8.row.col.f32.tf32.tf32.f32 "
        "{%0,%1,%2,%3}, {%4,%5,%6,%7}, {%8,%9}, {%0,%1,%2,%3};"
        : "+f"(c[0]), "+f"(c[1]), "+f"(c[2]), "+f"(c[3])
        : "r"(a[0]), "r"(a[1]), "r"(a[2]), "r"(a[3]), "r"(b[0]), "r"(b[1]));
}

// ============ tf32 mma.sync GEMM: Y[:,128] = X[NN,1024] @ Wt_half^T =========
// CTA tile 128M x 128N, BK=32, double-buffered, row-major + XOR-swizzled SMEM,
// ldmatrix-fed fragments. grid.x folds (mtile, z): z = bid & 1 -> Yl / Yr
// (adjacent bids share the A tile through L2).
//
// SMEM stage (32 KB): A 128 rows x 128B (tf32), B 128 rows x 128B.
// Swizzle: 16B-word w at row r lives at byte r*128 + ((w ^ (r&7))<<4).
#define GBK 32
#define NIT (IN_CHN / GBK)          // 32
#define STAGE_B 32768
#define GEMM_SMEM (2 * STAGE_B)     // 64 KB

__global__ void __launch_bounds__(256, 2)
gemm1_mma_kernel(const float* __restrict__ A)
{
    extern __shared__ char smc[];
    const uint32_t sbase = smem_u32(smc);
    const int tid = threadIdx.x;
    const int lane = tid & 31;
    const int wid = tid >> 5;
    const int warp_m = wid & 3;          // 0..3 (32 rows each)
    const int warp_n = wid >> 2;         // 0..1 (64 cols each)
    const int mtile = blockIdx.x >> 1;
    const int z     = blockIdx.x & 1;
    const int m0 = mtile * 128;
    const float* __restrict__ Bsrc = g_Wt + (size_t)z * 128 * IN_CHN;

    float acc[2][8][4];
    #pragma unroll
    for (int i = 0; i < 2; i++)
        #pragma unroll
        for (int j = 0; j < 8; j++)
            #pragma unroll
            for (int q = 0; q < 4; q++) acc[i][j][q] = 0.f;

    // staging indices: e4 = tid + p*256, row = e4>>3 (0..127), c4 = e4&7
    const int s_row = tid >> 3;          // row for p=0 (rows advance by 32 per p)
    const int s_c4  = tid & 7;

    auto stage = [&](int it, char* buf) {
        const int k0 = it * GBK;
        #pragma unroll
        for (int p = 0; p < 4; p++) {
            const int row = s_row + p * 32;
            const uint32_t soff = (uint32_t)row * 128 + (uint32_t)((s_c4 ^ (row & 7)) << 4);
            // A (convert to tf32)
            {
                int m = m0 + row;
                float4 v = make_float4(0.f, 0.f, 0.f, 0.f);
                if (m < NN) v = *(const float4*)(A + (size_t)m * IN_CHN + k0 + s_c4 * 4);
                uint4 t = make_uint4(f2tf32(v.x), f2tf32(v.y), f2tf32(v.z), f2tf32(v.w));
                *(uint4*)(buf + soff) = t;
            }
            // B (already tf32 in g_Wt)
            {
                uint4 t = *(const uint4*)(Bsrc + (size_t)row * IN_CHN + k0 + s_c4 * 4);
                *(uint4*)(buf + 16384 + soff) = t;
            }
        }
    };

    // ---- precomputed ldmatrix lane addressing (byte offsets within a stage) --
    // A matrices: id = lane>>3; for mfrag i: row = (warp_m*2+i)*16 + (id&1)*8 + (lane&7)
    //             word = ks*2 + (id>>1)
    const int lm_id   = lane >> 3;
    const int a_row0  = warp_m * 32 + (lm_id & 1) * 8 + (lane & 7);   // mfrag i adds i*16
    const int a_wsel  = lm_id >> 1;
    // B matrices: nf = warp_n*8 + p*2 + (id>>1); word = ks*2 + (id&1)
    //             row = nf*8 + (lane&7)
    const int b_row0  = warp_n * 64 + (lm_id >> 1) * 8 + (lane & 7);  // pair p adds p*16
    const int b_wsel  = lm_id & 1;

    stage(0, smc);
    __syncthreads();

    for (int it = 0; it < NIT; it++) {
        if (it + 1 < NIT) stage(it + 1, smc + ((it + 1) & 1) * STAGE_B);

        const uint32_t buf = sbase + (uint32_t)((it & 1) * STAGE_B);
        #pragma unroll
        for (int ks = 0; ks < 4; ks++) {
            uint32_t a[2][4];
            #pragma unroll
            for (int i = 0; i < 2; i++) {
                int row = a_row0 + i * 16;
                int w   = ks * 2 + a_wsel;
                ldsm4(a[i], buf + row * 128 + (((uint32_t)(w ^ (row & 7))) << 4));
            }
            uint32_t b[8][2];
            #pragma unroll
            for (int p = 0; p < 4; p++) {
                int row = b_row0 + p * 16;
                int w   = ks * 2 + b_wsel;
                uint32_t r[4];
                ldsm4(r, buf + 16384 + row * 128 + (((uint32_t)(w ^ (row & 7))) << 4));
                b[p * 2 + 0][0] = r[0];
                b[p * 2 + 0][1] = r[1];
                b[p * 2 + 1][0] = r[2];
                b[p * 2 + 1][1] = r[3];
            }
            #pragma unroll
            for (int i = 0; i < 2; i++)
                #pragma unroll
                for (int j = 0; j < 8; j++)
                    mma_tf32(acc[i][j], a[i], b[j]);
        }
        __syncthreads();
    }

    // ---- epilogue ----
    float* __restrict__ C = z ? g_Yr : g_Yl;
    const int g = lane >> 2, tig = lane & 3;
    #pragma unroll
    for (int i = 0; i < 2; i++) {
        int r0 = m0 + warp_m * 32 + i * 16 + g;
        #pragma unroll
        for (int j = 0; j < 8; j++) {
            int col = warp_n * 64 + j * 8 + tig * 2;
            if (r0 < NN)
                *(float2*)(C + (size_t)r0 * FC + col) = make_float2(acc[i][j][0], acc[i][j][1]);
            if (r0 + 8 < NN)
                *(float2*)(C + (size_t)(r0 + 8) * FC + col) = make_float2(acc[i][j][2], acc[i][j][3]);
        }
    }
}

// ---------------- prep: g_Wt[n][k] = tf32(W[k][n]) ---------------------------
__global__ void prep_wt_kernel(const float* __restrict__ Wl, const float* __restrict__ Wr) {
    int i = blockIdx.x * blockDim.x + threadIdx.x;
    if (i >= 256 * IN_CHN) return;
    int n = i >> 10;
    int k = i & 1023;
    float v = (n < FC) ? Wl[(size_t)k * FC + n] : Wr[(size_t)k * FC + (n - FC)];
    g_Wt[i] = __uint_as_float(f2tf32(v));
}

// ---------------- 0) zero the accumulators ---------------------------------
__global__ void zero_kernel() {
    size_t stride = (size_t)gridDim.x * blockDim.x;
    size_t i = (size_t)blockIdx.x * blockDim.x + threadIdx.x;
    for (size_t j = i; j < (size_t)NN * FC; j += stride) g_S[j] = 0.f;
    for (size_t j = i; j < (size_t)NN;      j += stride) g_deg[j] = 0.f;
    for (size_t j = i; j < (size_t)NN * OC; j += stride) g_S2[j] = 0.f;
}

// ---------------- 1) in-degree ----------------------------------------------
__global__ void deg_kernel(const int* __restrict__ edges) {
    int i = blockIdx.x * blockDim.x + threadIdx.x;
    if (i < NE) atomicAdd(&g_deg[edges[NE + i]], 1.0f);
}

// ---------------- 3) edge aggregation layer 1: S[dst] += Yl[src] -----------
// one warp per edge; lane holds a float4; vector reduction (sm_90+)
__global__ void agg1_kernel(const int* __restrict__ edges) {
    int gtid = blockIdx.x * blockDim.x + threadIdx.x;
    int e    = gtid >> 5;
    int lane = gtid & 31;
    if (e >= NE) return;
    int src = edges[e];
    int dst = edges[NE + e];
    float4 v = ((const float4*)(g_Yl + (size_t)src * FC))[lane];
    float* s = g_S + (size_t)dst * FC + lane * 4;
    asm volatile("red.global.add.v4.f32 [%0], {%1, %2, %3, %4};"
                 :: "l"(s), "f"(v.x), "f"(v.y), "f"(v.z), "f"(v.w) : "memory");
}

// ---------------- 4) x1 = leaky_relu(S/max(deg,1) + Yr + b1) ----------------
__global__ void finish1_kernel(const float* __restrict__ b1) {
    int i = blockIdx.x * blockDim.x + threadIdx.x;
    if (i >= NN * FC / 4) return;
    int node = i >> 5;
    int c4   = i & 31;
    float inv = 1.f / fmaxf(g_deg[node], 1.f);
    float4 s  = ((const float4*)g_S)[i];
    float4 yr = ((const float4*)g_Yr)[i];
    float4 b  = ((const float4*)b1)[c4];
    float4 o;
    o.x = s.x * inv + yr.x + b.x;
    o.y = s.y * inv + yr.y + b.y;
    o.z = s.z * inv + yr.z + b.z;
    o.w = s.w * inv + yr.w + b.w;
    o.x = o.x >= 0.f ? o.x : NEG_SLOPE * o.x;
    o.y = o.y >= 0.f ? o.y : NEG_SLOPE * o.y;
    o.z = o.z >= 0.f ? o.z : NEG_SLOPE * o.z;
    o.w = o.w >= 0.f ? o.w : NEG_SLOPE * o.w;
    ((float4*)g_x1)[i] = o;
}

// ---------------- 5) tiny GEMM layer 2 --------------------------------------
__global__ void gemm2_kernel(const float* __restrict__ W2l,
                             const float* __restrict__ W2r) {
    __shared__ float sWl[FC * OC];
    __shared__ float sWr[FC * OC];
    for (int t = threadIdx.x; t < FC * OC; t += blockDim.x) {
        sWl[t] = W2l[t];
        sWr[t] = W2r[t];
    }
    __syncthreads();

    int gtid = blockIdx.x * blockDim.x + threadIdx.x;
    int node = gtid >> 5;
    int lane = gtid & 31;
    if (node >= NN) return;

    float4 v = ((const float4*)(g_x1 + (size_t)node * FC))[lane];
    float vx[4] = {v.x, v.y, v.z, v.w};
    float al[OC] = {0.f, 0.f, 0.f};
    float arr[OC] = {0.f, 0.f, 0.f};
    #pragma unroll
    for (int u = 0; u < 4; u++) {
        int k = lane * 4 + u;
        #pragma unroll
        for (int c = 0; c < OC; c++) {
            al[c]  = fmaf(vx[u], sWl[k * OC + c], al[c]);
            arr[c] = fmaf(vx[u], sWr[k * OC + c], arr[c]);
        }
    }
    #pragma unroll
    for (int off = 16; off > 0; off >>= 1) {
        #pragma unroll
        for (int c = 0; c < OC; c++) {
            al[c]  += __shfl_xor_sync(0xFFFFFFFFu, al[c],  off);
            arr[c] += __shfl_xor_sync(0xFFFFFFFFu, arr[c], off);
        }
    }
    if (lane == 0) {
        #pragma unroll
        for (int c = 0; c < OC; c++) {
            g_Zl[node * OC + c] = al[c];
            g_Zr[node * OC + c] = arr[c];
        }
    }
}

// ---------------- 6) edge aggregation layer 2 -------------------------------
__global__ void agg2_kernel(const int* __restrict__ edges) {
    int e = blockIdx.x * blockDim.x + threadIdx.x;
    if (e >= NE) return;
    int src = edges[e];
    int dst = edges[NE + e];
    #pragma unroll
    for (int c = 0; c < OC; c++)
        atomicAdd(&g_S2[dst * OC + c], g_Zl[src * OC + c]);
}

// ---------------- 7) out = S2/max(deg,1) + Zr + b2 ---------------------------
__global__ void final_kernel(const float* __restrict__ b2,
                             float* __restrict__ out) {
    int i = blockIdx.x * blockDim.x + threadIdx.x;
    if (i >= NN * OC) return;
    int node = i / OC;
    int c = i - node * OC;
    float inv = 1.f / fmaxf(g_deg[node], 1.f);
    out[i] = g_S2[i] * inv + g_Zr[i] + b2[c];
}

// ---------------- launch -----------------------------------------------------
extern "C" void kernel_launch(void* const* d_in, const int* in_sizes, int n_in,
                              void* d_out, int out_size) {
    const float* features = (const float*)d_in[0];
    const int*   edges2   = (const int*)d_in[2];   // int32 (jax default, no x64)
    const float* W1_l     = (const float*)d_in[5];
    const float* W1_r     = (const float*)d_in[6];
    const float* b1       = (const float*)d_in[7];
    const float* W2_l     = (const float*)d_in[8];
    const float* W2_r     = (const float*)d_in[9];
    const float* b2       = (const float*)d_in[10];
    float*       out      = (float*)d_out;

    static bool attr_set = false;
    if (!attr_set) {
        cudaFuncSetAttribute(gemm1_mma_kernel,
                             cudaFuncAttributeMaxDynamicSharedMemorySize, GEMM_SMEM);
        attr_set = true;
    }

    zero_kernel<<<2048, 256>>>();
    deg_kernel<<<(NE + 255) / 256, 256>>>(edges2);
    prep_wt_kernel<<<(256 * IN_CHN + 255) / 256, 256>>>(W1_l, W1_r);

    gemm1_mma_kernel<<<((NN + 127) / 128) * 2, 256, GEMM_SMEM>>>(features);

    agg1_kernel<<<(NE * 32 + 255) / 256, 256>>>(edges2);
    finish1_kernel<<<(NN * FC / 4 + 255) / 256, 256>>>(b1);
    gemm2_kernel<<<(NN * 32 + 255) / 256, 256>>>(W2_l, W2_r);
    agg2_kernel<<<(NE + 255) / 256, 256>>>(edges2);
    final_kernel<<<(NN * OC + 255) / 256, 256>>>(b2, out);
}

// round 15
// speedup vs baseline: 1.0028x; 1.0026x over previous
#include <cuda_runtime.h>
#include <cstdint>

#define NN      100000
#define NE      400000
#define IN_CHN  1024
#define FC      128
#define OC      3
#define NEG_SLOPE 0.01f

// ---------------- scratch (static device globals; no allocation) ------------
__device__ __align__(16) float g_Yl[(size_t)NN * FC];   // X @ W1_l
__device__ __align__(16) float g_Yr[(size_t)NN * FC];   // X @ W1_r
__device__ __align__(16) float g_S [(size_t)NN * FC];   // segment-sum of Yl
__device__ __align__(16) float g_x1[(size_t)NN * FC];   // layer-1 output
__device__ __align__(16) float g_deg[NN];
__device__ __align__(16) float g_Wt[256 * IN_CHN];      // [Wl|Wr]^T, K-major, tf32
__device__ __align__(16) float g_Zl[NN * OC + 4];
__device__ __align__(16) float g_Zr[NN * OC + 4];
__device__ __align__(16) float g_S2[NN * OC + 4];

__device__ __forceinline__ uint32_t f2tf32(float x) {
    uint32_t r;
    asm("cvt.rna.tf32.f32 %0, %1;" : "=r"(r) : "f"(x));
    return r;
}
__device__ __forceinline__ uint32_t smem_u32(const void* p) {
    uint32_t a;
    asm("{ .reg .u64 t; cvta.to.shared.u64 t, %1; cvt.u32.u64 %0, t; }" : "=r"(a) : "l"(p));
    return a;
}
__device__ __forceinline__ void ldsm4(uint32_t* r, uint32_t addr) {
    asm volatile("ldmatrix.sync.aligned.m8n8.x4.shared.b16 {%0,%1,%2,%3}, [%4];"
        : "=r"(r[0]), "=r"(r[1]), "=r"(r[2]), "=r"(r[3]) : "r"(addr));
}
__device__ __forceinline__ void mma_tf32(float* c, const uint32_t* a, const uint32_t* b) {
    asm volatile(
        "mma.sync.aligned.m16n8k8.row.col.f32.tf32.tf32.f32 "
        "{%0,%1,%2,%3}, {%4,%5,%6,%7}, {%8,%9}, {%0,%1,%2,%3};"
        : "+f"(c[0]), "+f"(c[1]), "+f"(c[2]), "+f"(c[3])
        : "r"(a[0]), "r"(a[1]), "r"(a[2]), "r"(a[3]), "r"(b[0]), "r"(b[1]));
}

// ============ tf32 mma.sync GEMM: Y[:,128] = X[NN,1024] @ Wt_half^T =========
// CTA tile 128M x 128N, BK=32, double-buffered, row-major + XOR-swizzled SMEM,
// ldmatrix-fed fragments. grid.x folds (mtile, z): z = bid & 1 -> Yl / Yr
// (adjacent bids share the A tile through L2).
//
// SMEM stage (32 KB): A 128 rows x 128B (tf32), B 128 rows x 128B.
// Swizzle: 16B-word w at row r lives at byte r*128 + ((w ^ (r&7))<<4).
#define GBK 32
#define NIT (IN_CHN / GBK)          // 32
#define STAGE_B 32768
#define GEMM_SMEM (2 * STAGE_B)     // 64 KB

__global__ void __launch_bounds__(256, 2)
gemm1_mma_kernel(const float* __restrict__ A)
{
    extern __shared__ char smc[];
    const uint32_t sbase = smem_u32(smc);
    const int tid = threadIdx.x;
    const int lane = tid & 31;
    const int wid = tid >> 5;
    const int warp_m = wid & 3;          // 0..3 (32 rows each)
    const int warp_n = wid >> 2;         // 0..1 (64 cols each)
    const int mtile = blockIdx.x >> 1;
    const int z     = blockIdx.x & 1;
    const int m0 = mtile * 128;
    const float* __restrict__ Bsrc = g_Wt + (size_t)z * 128 * IN_CHN;

    float acc[2][8][4];
    #pragma unroll
    for (int i = 0; i < 2; i++)
        #pragma unroll
        for (int j = 0; j < 8; j++)
            #pragma unroll
            for (int q = 0; q < 4; q++) acc[i][j][q] = 0.f;

    // staging indices: e4 = tid + p*256, row = e4>>3 (0..127), c4 = e4&7
    const int s_row = tid >> 3;          // row for p=0 (rows advance by 32 per p)
    const int s_c4  = tid & 7;

    auto stage = [&](int it, char* buf) {
        const int k0 = it * GBK;
        #pragma unroll
        for (int p = 0; p < 4; p++) {
            const int row = s_row + p * 32;
            const uint32_t soff = (uint32_t)row * 128 + (uint32_t)((s_c4 ^ (row & 7)) << 4);
            // A (convert to tf32)
            {
                int m = m0 + row;
                float4 v = make_float4(0.f, 0.f, 0.f, 0.f);
                if (m < NN) v = *(const float4*)(A + (size_t)m * IN_CHN + k0 + s_c4 * 4);
                uint4 t = make_uint4(f2tf32(v.x), f2tf32(v.y), f2tf32(v.z), f2tf32(v.w));
                *(uint4*)(buf + soff) = t;
            }
            // B (already tf32 in g_Wt)
            {
                uint4 t = *(const uint4*)(Bsrc + (size_t)row * IN_CHN + k0 + s_c4 * 4);
                *(uint4*)(buf + 16384 + soff) = t;
            }
        }
    };

    // ---- precomputed ldmatrix lane addressing (byte offsets within a stage) --
    // A matrices: id = lane>>3; for mfrag i: row = (warp_m*2+i)*16 + (id&1)*8 + (lane&7)
    //             word = ks*2 + (id>>1)
    const int lm_id   = lane >> 3;
    const int a_row0  = warp_m * 32 + (lm_id & 1) * 8 + (lane & 7);   // mfrag i adds i*16
    const int a_wsel  = lm_id >> 1;
    // B matrices: nf = warp_n*8 + p*2 + (id>>1); word = ks*2 + (id&1)
    //             row = nf*8 + (lane&7)
    const int b_row0  = warp_n * 64 + (lm_id >> 1) * 8 + (lane & 7);  // pair p adds p*16
    const int b_wsel  = lm_id & 1;

    stage(0, smc);
    __syncthreads();

    for (int it = 0; it < NIT; it++) {
        if (it + 1 < NIT) stage(it + 1, smc + ((it + 1) & 1) * STAGE_B);

        const uint32_t buf = sbase + (uint32_t)((it & 1) * STAGE_B);
        #pragma unroll
        for (int ks = 0; ks < 4; ks++) {
            uint32_t a[2][4];
            #pragma unroll
            for (int i = 0; i < 2; i++) {
                int row = a_row0 + i * 16;
                int w   = ks * 2 + a_wsel;
                ldsm4(a[i], buf + row * 128 + (((uint32_t)(w ^ (row & 7))) << 4));
            }
            uint32_t b[8][2];
            #pragma unroll
            for (int p = 0; p < 4; p++) {
                int row = b_row0 + p * 16;
                int w   = ks * 2 + b_wsel;
                uint32_t r[4];
                ldsm4(r, buf + 16384 + row * 128 + (((uint32_t)(w ^ (row & 7))) << 4));
                b[p * 2 + 0][0] = r[0];
                b[p * 2 + 0][1] = r[1];
                b[p * 2 + 1][0] = r[2];
                b[p * 2 + 1][1] = r[3];
            }
            #pragma unroll
            for (int i = 0; i < 2; i++)
                #pragma unroll
                for (int j = 0; j < 8; j++)
                    mma_tf32(acc[i][j], a[i], b[j]);
        }
        __syncthreads();
    }

    // ---- epilogue ----
    float* __restrict__ C = z ? g_Yr : g_Yl;
    const int g = lane >> 2, tig = lane & 3;
    #pragma unroll
    for (int i = 0; i < 2; i++) {
        int r0 = m0 + warp_m * 32 + i * 16 + g;
        #pragma unroll
        for (int j = 0; j < 8; j++) {
            int col = warp_n * 64 + j * 8 + tig * 2;
            if (r0 < NN)
                *(float2*)(C + (size_t)r0 * FC + col) = make_float2(acc[i][j][0], acc[i][j][1]);
            if (r0 + 8 < NN)
                *(float2*)(C + (size_t)(r0 + 8) * FC + col) = make_float2(acc[i][j][2], acc[i][j][3]);
        }
    }
}

// ---------------- prep: g_Wt[n][k] = tf32(W[k][n]) ---------------------------
__global__ void prep_wt_kernel(const float* __restrict__ Wl, const float* __restrict__ Wr) {
    int i = blockIdx.x * blockDim.x + threadIdx.x;
    if (i >= 256 * IN_CHN) return;
    int n = i >> 10;
    int k = i & 1023;
    float v = (n < FC) ? Wl[(size_t)k * FC + n] : Wr[(size_t)k * FC + (n - FC)];
    g_Wt[i] = __uint_as_float(f2tf32(v));
}

// ---------------- 0) zero the accumulators ---------------------------------
__global__ void zero_kernel() {
    size_t stride = (size_t)gridDim.x * blockDim.x;
    size_t i = (size_t)blockIdx.x * blockDim.x + threadIdx.x;
    for (size_t j = i; j < (size_t)NN * FC; j += stride) g_S[j] = 0.f;
    for (size_t j = i; j < (size_t)NN;      j += stride) g_deg[j] = 0.f;
    for (size_t j = i; j < (size_t)NN * OC; j += stride) g_S2[j] = 0.f;
}

// ---------------- 1) in-degree ----------------------------------------------
__global__ void deg_kernel(const int* __restrict__ edges) {
    int i = blockIdx.x * blockDim.x + threadIdx.x;
    if (i < NE) atomicAdd(&g_deg[edges[NE + i]], 1.0f);
}

// ---------------- 3) edge aggregation layer 1: S[dst] += Yl[src] -----------
// one warp per edge; lane holds a float4; vector reduction (sm_90+)
__global__ void agg1_kernel(const int* __restrict__ edges) {
    int gtid = blockIdx.x * blockDim.x + threadIdx.x;
    int e    = gtid >> 5;
    int lane = gtid & 31;
    if (e >= NE) return;
    int src = edges[e];
    int dst = edges[NE + e];
    float4 v = ((const float4*)(g_Yl + (size_t)src * FC))[lane];
    float* s = g_S + (size_t)dst * FC + lane * 4;
    asm volatile("red.global.add.v4.f32 [%0], {%1, %2, %3, %4};"
                 :: "l"(s), "f"(v.x), "f"(v.y), "f"(v.z), "f"(v.w) : "memory");
}

// ---------------- 4) x1 = leaky_relu(S/max(deg,1) + Yr + b1) ----------------
__global__ void finish1_kernel(const float* __restrict__ b1) {
    int i = blockIdx.x * blockDim.x + threadIdx.x;
    if (i >= NN * FC / 4) return;
    int node = i >> 5;
    int c4   = i & 31;
    float inv = 1.f / fmaxf(g_deg[node], 1.f);
    float4 s  = ((const float4*)g_S)[i];
    float4 yr = ((const float4*)g_Yr)[i];
    float4 b  = ((const float4*)b1)[c4];
    float4 o;
    o.x = s.x * inv + yr.x + b.x;
    o.y = s.y * inv + yr.y + b.y;
    o.z = s.z * inv + yr.z + b.z;
    o.w = s.w * inv + yr.w + b.w;
    o.x = o.x >= 0.f ? o.x : NEG_SLOPE * o.x;
    o.y = o.y >= 0.f ? o.y : NEG_SLOPE * o.y;
    o.z = o.z >= 0.f ? o.z : NEG_SLOPE * o.z;
    o.w = o.w >= 0.f ? o.w : NEG_SLOPE * o.w;
    ((float4*)g_x1)[i] = o;
}

// ---------------- 5) tiny GEMM layer 2 --------------------------------------
__global__ void gemm2_kernel(const float* __restrict__ W2l,
                             const float* __restrict__ W2r) {
    __shared__ float sWl[FC * OC];
    __shared__ float sWr[FC * OC];
    for (int t = threadIdx.x; t < FC * OC; t += blockDim.x) {
        sWl[t] = W2l[t];
        sWr[t] = W2r[t];
    }
    __syncthreads();

    int gtid = blockIdx.x * blockDim.x + threadIdx.x;
    int node = gtid >> 5;
    int lane = gtid & 31;
    if (node >= NN) return;

    float4 v = ((const float4*)(g_x1 + (size_t)node * FC))[lane];
    float vx[4] = {v.x, v.y, v.z, v.w};
    float al[OC] = {0.f, 0.f, 0.f};
    float arr[OC] = {0.f, 0.f, 0.f};
    #pragma unroll
    for (int u = 0; u < 4; u++) {
        int k = lane * 4 + u;
        #pragma unroll
        for (int c = 0; c < OC; c++) {
            al[c]  = fmaf(vx[u], sWl[k * OC + c], al[c]);
            arr[c] = fmaf(vx[u], sWr[k * OC + c], arr[c]);
        }
    }
    #pragma unroll
    for (int off = 16; off > 0; off >>= 1) {
        #pragma unroll
        for (int c = 0; c < OC; c++) {
            al[c]  += __shfl_xor_sync(0xFFFFFFFFu, al[c],  off);
            arr[c] += __shfl_xor_sync(0xFFFFFFFFu, arr[c], off);
        }
    }
    if (lane == 0) {
        #pragma unroll
        for (int c = 0; c < OC; c++) {
            g_Zl[node * OC + c] = al[c];
            g_Zr[node * OC + c] = arr[c];
        }
    }
}

// ---------------- 6) edge aggregation layer 2 -------------------------------
__global__ void agg2_kernel(const int* __restrict__ edges) {
    int e = blockIdx.x * blockDim.x + threadIdx.x;
    if (e >= NE) return;
    int src = edges[e];
    int dst = edges[NE + e];
    #pragma unroll
    for (int c = 0; c < OC; c++)
        atomicAdd(&g_S2[dst * OC + c], g_Zl[src * OC + c]);
}

// ---------------- 7) out = S2/max(deg,1) + Zr + b2 ---------------------------
__global__ void final_kernel(const float* __restrict__ b2,
                             float* __restrict__ out) {
    int i = blockIdx.x * blockDim.x + threadIdx.x;
    if (i >= NN * OC) return;
    int node = i / OC;
    int c = i - node * OC;
    float inv = 1.f / fmaxf(g_deg[node], 1.f);
    out[i] = g_S2[i] * inv + g_Zr[i] + b2[c];
}

// ---------------- launch -----------------------------------------------------
extern "C" void kernel_launch(void* const* d_in, const int* in_sizes, int n_in,
                              void* d_out, int out_size) {
    const float* features = (const float*)d_in[0];
    const int*   edges2   = (const int*)d_in[2];   // int32 (jax default, no x64)
    const float* W1_l     = (const float*)d_in[5];
    const float* W1_r     = (const float*)d_in[6];
    const float* b1       = (const float*)d_in[7];
    const float* W2_l     = (const float*)d_in[8];
    const float* W2_r     = (const float*)d_in[9];
    const float* b2       = (const float*)d_in[10];
    float*       out      = (float*)d_out;

    static bool attr_set = false;
    if (!attr_set) {
        cudaFuncSetAttribute(gemm1_mma_kernel,
                             cudaFuncAttributeMaxDynamicSharedMemorySize, GEMM_SMEM);
        attr_set = true;
    }

    zero_kernel<<<2048, 256>>>();
    deg_kernel<<<(NE + 255) / 256, 256>>>(edges2);
    prep_wt_kernel<<<(256 * IN_CHN + 255) / 256, 256>>>(W1_l, W1_r);

    gemm1_mma_kernel<<<((NN + 127) / 128) * 2, 256, GEMM_SMEM>>>(features);

    agg1_kernel<<<(NE * 32 + 255) / 256, 256>>>(edges2);
    finish1_kernel<<<(NN * FC / 4 + 255) / 256, 256>>>(b1);
    gemm2_kernel<<<(NN * 32 + 255) / 256, 256>>>(W2_l, W2_r);
    agg2_kernel<<<(NE + 255) / 256, 256>>>(edges2);
    final_kernel<<<(NN * OC + 255) / 256, 256>>>(b2, out);
}